// round 15
// baseline (speedup 1.0000x reference)
#include <cuda_runtime.h>
#include <math.h>
#include <stdint.h>

// Problem shapes (fixed by the dataset)
#define B  32
#define C  512
#define D  4096
#define H  128        // hidden
#define NROWS (B * C) // 16384

// Pool kernel: warp-private cp.async pipelines
#define PR      128          // rows per block == threads per block (4 warps)
#define PCH     16           // columns per chunk
#define NCH     (D / PCH)    // 256 chunks
#define NSTAGE  4            // smem ring depth (power of 2)
#define SSTRIDE 20           // floats per row slot (16 + 4 pad; 80B, 16B-aligned)

// Scratch (no cudaMalloc allowed)
__device__ float g_pooled[B * C];
__device__ int   g_ord[B * C];

// ---------------------------------------------------------------------------
// Bit-faithful XLA-CPU vectorized expf. PROVEN: rel_err == 0.0. DO NOT MODIFY.
// ---------------------------------------------------------------------------
__device__ __forceinline__ float xla_cpu_expf(float x) {
    const float exp_hi = 88.3762626647950f;
    const float exp_lo = -88.3762626647949f;
    const float LOG2EF = 1.44269504088896341f;
    const float C1 = 0.693359375f;
    const float C2 = -2.12194440e-4f;
    const float p0 = 1.9875691500e-4f;
    const float p1 = 1.3981999507e-3f;
    const float p2 = 8.3334519073e-3f;
    const float p3 = 4.1665795894e-2f;
    const float p4 = 1.6666665459e-1f;
    const float p5 = 5.0000001201e-1f;

    x = fminf(fmaxf(x, exp_lo), exp_hi);

    float fx = __fadd_rn(__fmul_rn(x, LOG2EF), 0.5f);
    fx = floorf(fx);

    float tmp = __fmul_rn(fx, C1);
    float z   = __fmul_rn(fx, C2);
    x = __fsub_rn(x, tmp);
    x = __fsub_rn(x, z);
    z = __fmul_rn(x, x);

    float y = p0;
    y = __fadd_rn(__fmul_rn(y, x), p1);
    y = __fadd_rn(__fmul_rn(y, x), p2);
    y = __fadd_rn(__fmul_rn(y, x), p3);
    y = __fadd_rn(__fmul_rn(y, x), p4);
    y = __fadd_rn(__fmul_rn(y, x), p5);
    y = __fadd_rn(__fmul_rn(y, z), x);
    y = __fadd_rn(y, 1.0f);

    int n = (int)fx;
    y = __fmul_rn(y, __int_as_float((n + 127) << 23));
    return y;
}

// ---------------------------------------------------------------------------
// Kernel A: pooled[row] = (strict sequential fp32 sum over d) * (1/4096).
// IDENTICAL addition order to round 8 (bit-exact). Scheduling: per-WARP
// cp.async pipelines — warp w copies exactly rows [32w, 32w+32) that its own
// lanes consume, so chunk handoff needs only cp.async.wait_group + syncwarp
// (cp.async groups are per-thread; producers and consumers share a warp).
// No __syncthreads in the main loop; warps run fully decoupled.
// Slot algebra: issue 0..2 up front; each iter waits<=2 (chunk ch resident),
// refills slot (ch+3)&3 (distinct from consume slot ch&3); the syncwarp at
// iter ch+1 fences all lanes' chunk-ch reads before slot reuse at ch+4.
// ---------------------------------------------------------------------------
__global__ void __launch_bounds__(PR) pool_kernel(const float* __restrict__ x) {
    __shared__ float ring[NSTAGE][PR * SSTRIDE];   // 4 * 128*20*4B = 40 KB

    const int tid  = threadIdx.x;
    const int wid  = tid >> 5;            // warp id (0..3)
    const int lane = tid & 31;
    const int base = blockIdx.x * PR;
    const int wrow = wid << 5;            // first row of this warp's band
    const float4* __restrict__ x4 = reinterpret_cast<const float4*>(x);

    // Per-warp stage issue: 32 rows x 4 float4 = 128 copies, 4 per lane.
    // g = lane + it*32: r_local = g>>2 (0..31), c4 = g&3.
    // Coalescing: 4 consecutive lanes cover one 64B row segment.
#define ISSUE_STAGE(CH)                                                        \
    do {                                                                       \
        const int _s = (CH) & (NSTAGE - 1);                                    \
        _Pragma("unroll")                                                      \
        for (int _it = 0; _it < 4; ++_it) {                                    \
            const int _g  = lane + _it * 32;                                   \
            const int _r  = wrow + (_g >> 2);                                  \
            const int _c4 = _g & 3;                                            \
            const float4* _src = &x4[(size_t)(base + _r) * (D / 4)             \
                                     + (size_t)(CH) * (PCH / 4) + _c4];        \
            uint32_t _dst = (uint32_t)__cvta_generic_to_shared(                \
                &ring[_s][_r * SSTRIDE + _c4 * 4]);                            \
            asm volatile("cp.async.cg.shared.global [%0], [%1], 16;"           \
                         :: "r"(_dst), "l"(_src) : "memory");                  \
        }                                                                      \
        asm volatile("cp.async.commit_group;" ::: "memory");                   \
    } while (0)

    ISSUE_STAGE(0);
    ISSUE_STAGE(1);
    ISSUE_STAGE(2);

    float acc = 0.f;
    for (int ch = 0; ch < NCH; ++ch) {
        asm volatile("cp.async.wait_group 2;" ::: "memory");
        __syncwarp();      // producers == this warp's lanes: make their
                           // cp.async writes visible; fence prior reads.

        // Refill first (overlaps the add chain below).
        if (ch + 3 < NCH) {
            ISSUE_STAGE(ch + 3);
        } else {
            asm volatile("cp.async.commit_group;" ::: "memory"); // empty group
        }

        // Strict sequential accumulation over this chunk's 16 columns.
        const int s = ch & (NSTAGE - 1);
        const float4* rowp =
            reinterpret_cast<const float4*>(&ring[s][tid * SSTRIDE]);
#pragma unroll
        for (int i4 = 0; i4 < PCH / 4; ++i4) {
            float4 v = rowp[i4];
            acc = __fadd_rn(acc, v.x);
            acc = __fadd_rn(acc, v.y);
            acc = __fadd_rn(acc, v.z);
            acc = __fadd_rn(acc, v.w);
        }
    }
#undef ISSUE_STAGE

    g_pooled[base + tid] = __fmul_rn(acc, (1.0f / (float)D));
}

// ---------------------------------------------------------------------------
// Kernel B: per batch-item (grid = 32, block = 512), fp32 throughout.
// PROVEN bit-exact (rel_err==0.0). DO NOT MODIFY ARITHMETIC.
// ---------------------------------------------------------------------------
__global__ void __launch_bounds__(512) mlp_sort_kernel(
    const float* __restrict__ W1, const float* __restrict__ b1,
    const float* __restrict__ W2, const float* __restrict__ b2) {
    const int b   = blockIdx.x;
    const int tid = threadIdx.x;

    __shared__ float ps[C];
    __shared__ float hs[H];
    __shared__ float ss[C];
    __shared__ int   si[C];

    ps[tid] = g_pooled[b * C + tid];
    __syncthreads();

    if (tid < H) {
        const float* __restrict__ w = W1 + tid * C;
        float acc = 0.f;
        for (int k = 0; k < C; k++) acc = fmaf(w[k], ps[k], acc);
        acc = __fadd_rn(acc, b1[tid]);
        hs[tid] = (acc >= 0.f) ? acc : __fmul_rn(0.01f, acc);
    }
    __syncthreads();

    {
        const float* __restrict__ w = W2 + tid * H;
        float acc = 0.f;
        for (int k = 0; k < H; k++) acc = fmaf(w[k], hs[k], acc);
        acc = __fadd_rn(acc, b2[tid]);
        float e = xla_cpu_expf(-acc);
        ss[tid] = __fdiv_rn(1.0f, __fadd_rn(1.0f, e));
        si[tid] = tid;
    }
    __syncthreads();

    // Bitonic sort, 512 elems, key = (score desc, idx asc).
    for (int k = 2; k <= C; k <<= 1) {
        for (int j = k >> 1; j > 0; j >>= 1) {
            const int i   = tid;
            const int ixj = i ^ j;
            if (ixj > i) {
                const float a_s = ss[i],  b_s = ss[ixj];
                const int   a_i = si[i],  b_i = si[ixj];
                const bool b_precedes_a = (b_s > a_s) || (b_s == a_s && b_i < a_i);
                const bool a_precedes_b = (a_s > b_s) || (a_s == b_s && a_i < b_i);
                const bool up = ((i & k) == 0);
                const bool do_swap = up ? b_precedes_a : a_precedes_b;
                if (do_swap) {
                    ss[i] = b_s; ss[ixj] = a_s;
                    si[i] = b_i; si[ixj] = a_i;
                }
            }
            __syncthreads();
        }
    }

    g_ord[b * C + tid] = si[tid];
}

// ---------------------------------------------------------------------------
// Kernel C: out[b,c,:] = x[b,c,:] + x[b, ord[b][c], :]
// b-major grid -> gathered read re-hits L2 (8 MiB/batch << 126 MB).
// All 8 loads issued before any arithmetic (8 outstanding LDG.128/thread);
// streaming stores (__stcs) keep out from evicting x slices in L2.
// ---------------------------------------------------------------------------
__global__ void __launch_bounds__(256) shuffle_add_kernel(
    const float* __restrict__ x, float* __restrict__ out) {
    const int row = blockIdx.x;          // b*512 + c
    const int b   = row >> 9;
    const int src = g_ord[row];

    const float4* __restrict__ xa =
        reinterpret_cast<const float4*>(x + (size_t)row * D);
    const float4* __restrict__ xb =
        reinterpret_cast<const float4*>(x + ((size_t)(b << 9) + src) * D);
    float4* __restrict__ o = reinterpret_cast<float4*>(out + (size_t)row * D);

    const int t = threadIdx.x;
    float4 a[4], g[4];
#pragma unroll
    for (int i = 0; i < 4; ++i) a[i] = xa[t + i * 256];
#pragma unroll
    for (int i = 0; i < 4; ++i) g[i] = xb[t + i * 256];
#pragma unroll
    for (int i = 0; i < 4; ++i) {
        float4 r;
        r.x = a[i].x + g[i].x;
        r.y = a[i].y + g[i].y;
        r.z = a[i].z + g[i].z;
        r.w = a[i].w + g[i].w;
        __stcs(&o[t + i * 256], r);
    }
}

// ---------------------------------------------------------------------------
extern "C" void kernel_launch(void* const* d_in, const int* in_sizes, int n_in,
                              void* d_out, int out_size) {
    const float* x  = (const float*)d_in[0];
    const float* W1 = (const float*)d_in[1];
    const float* b1 = (const float*)d_in[2];
    const float* W2 = (const float*)d_in[3];
    const float* b2 = (const float*)d_in[4];
    float* out = (float*)d_out;

    pool_kernel<<<NROWS / PR, PR>>>(x);
    mlp_sort_kernel<<<B, 512>>>(W1, b1, W2, b2);
    shuffle_add_kernel<<<NROWS, 256>>>(x, out);
}

// round 16
// speedup vs baseline: 1.0185x; 1.0185x over previous
#include <cuda_runtime.h>
#include <math.h>
#include <stdint.h>

// Problem shapes (fixed by the dataset)
#define B  32
#define C  512
#define D  4096
#define H  128        // hidden
#define NROWS (B * C) // 16384

// Pool kernel: warp-private cp.async pipelines
#define PR      128          // rows per block == threads per block (4 warps)
#define PCH     16           // columns per chunk
#define NCH     (D / PCH)    // 256 chunks
#define NSTAGE  4            // smem ring depth (power of 2)
#define SSTRIDE 20           // floats per row slot (16 + 4 pad; 80B, 16B-aligned)

// Scratch (no cudaMalloc allowed)
__device__ float g_pooled[B * C];
__device__ int   g_ord[B * C];

// ---------------------------------------------------------------------------
// Bit-faithful XLA-CPU vectorized expf. PROVEN: rel_err == 0.0. DO NOT MODIFY.
// ---------------------------------------------------------------------------
__device__ __forceinline__ float xla_cpu_expf(float x) {
    const float exp_hi = 88.3762626647950f;
    const float exp_lo = -88.3762626647949f;
    const float LOG2EF = 1.44269504088896341f;
    const float C1 = 0.693359375f;
    const float C2 = -2.12194440e-4f;
    const float p0 = 1.9875691500e-4f;
    const float p1 = 1.3981999507e-3f;
    const float p2 = 8.3334519073e-3f;
    const float p3 = 4.1665795894e-2f;
    const float p4 = 1.6666665459e-1f;
    const float p5 = 5.0000001201e-1f;

    x = fminf(fmaxf(x, exp_lo), exp_hi);

    float fx = __fadd_rn(__fmul_rn(x, LOG2EF), 0.5f);
    fx = floorf(fx);

    float tmp = __fmul_rn(fx, C1);
    float z   = __fmul_rn(fx, C2);
    x = __fsub_rn(x, tmp);
    x = __fsub_rn(x, z);
    z = __fmul_rn(x, x);

    float y = p0;
    y = __fadd_rn(__fmul_rn(y, x), p1);
    y = __fadd_rn(__fmul_rn(y, x), p2);
    y = __fadd_rn(__fmul_rn(y, x), p3);
    y = __fadd_rn(__fmul_rn(y, x), p4);
    y = __fadd_rn(__fmul_rn(y, x), p5);
    y = __fadd_rn(__fmul_rn(y, z), x);
    y = __fadd_rn(y, 1.0f);

    int n = (int)fx;
    y = __fmul_rn(y, __int_as_float((n + 127) << 23));
    return y;
}

// ---------------------------------------------------------------------------
// Kernel A: pooled[row] = (strict sequential fp32 sum over d) * (1/4096).
// IDENTICAL addition order to round 8 (bit-exact). Scheduling: per-WARP
// cp.async pipelines — warp w copies exactly rows [32w, 32w+32) that its own
// lanes consume, so chunk handoff needs only cp.async.wait_group + syncwarp
// (cp.async groups are per-thread; producers and consumers share a warp).
// No __syncthreads in the main loop; warps run fully decoupled.
// Slot algebra: issue 0..2 up front; each iter waits<=2 (chunk ch resident),
// refills slot (ch+3)&3 (distinct from consume slot ch&3); the syncwarp at
// iter ch+1 fences all lanes' chunk-ch reads before slot reuse at ch+4.
// ---------------------------------------------------------------------------
__global__ void __launch_bounds__(PR) pool_kernel(const float* __restrict__ x) {
    __shared__ float ring[NSTAGE][PR * SSTRIDE];   // 4 * 128*20*4B = 40 KB

    const int tid  = threadIdx.x;
    const int wid  = tid >> 5;            // warp id (0..3)
    const int lane = tid & 31;
    const int base = blockIdx.x * PR;
    const int wrow = wid << 5;            // first row of this warp's band
    const float4* __restrict__ x4 = reinterpret_cast<const float4*>(x);

    // Per-warp stage issue: 32 rows x 4 float4 = 128 copies, 4 per lane.
    // g = lane + it*32: r_local = g>>2 (0..31), c4 = g&3.
    // Coalescing: 4 consecutive lanes cover one 64B row segment.
#define ISSUE_STAGE(CH)                                                        \
    do {                                                                       \
        const int _s = (CH) & (NSTAGE - 1);                                    \
        _Pragma("unroll")                                                      \
        for (int _it = 0; _it < 4; ++_it) {                                    \
            const int _g  = lane + _it * 32;                                   \
            const int _r  = wrow + (_g >> 2);                                  \
            const int _c4 = _g & 3;                                            \
            const float4* _src = &x4[(size_t)(base + _r) * (D / 4)             \
                                     + (size_t)(CH) * (PCH / 4) + _c4];        \
            uint32_t _dst = (uint32_t)__cvta_generic_to_shared(                \
                &ring[_s][_r * SSTRIDE + _c4 * 4]);                            \
            asm volatile("cp.async.cg.shared.global [%0], [%1], 16;"           \
                         :: "r"(_dst), "l"(_src) : "memory");                  \
        }                                                                      \
        asm volatile("cp.async.commit_group;" ::: "memory");                   \
    } while (0)

    ISSUE_STAGE(0);
    ISSUE_STAGE(1);
    ISSUE_STAGE(2);

    float acc = 0.f;
    for (int ch = 0; ch < NCH; ++ch) {
        asm volatile("cp.async.wait_group 2;" ::: "memory");
        __syncwarp();      // producers == this warp's lanes: make their
                           // cp.async writes visible; fence prior reads.

        // Refill first (overlaps the add chain below).
        if (ch + 3 < NCH) {
            ISSUE_STAGE(ch + 3);
        } else {
            asm volatile("cp.async.commit_group;" ::: "memory"); // empty group
        }

        // Strict sequential accumulation over this chunk's 16 columns.
        const int s = ch & (NSTAGE - 1);
        const float4* rowp =
            reinterpret_cast<const float4*>(&ring[s][tid * SSTRIDE]);
#pragma unroll
        for (int i4 = 0; i4 < PCH / 4; ++i4) {
            float4 v = rowp[i4];
            acc = __fadd_rn(acc, v.x);
            acc = __fadd_rn(acc, v.y);
            acc = __fadd_rn(acc, v.z);
            acc = __fadd_rn(acc, v.w);
        }
    }
#undef ISSUE_STAGE

    g_pooled[base + tid] = __fmul_rn(acc, (1.0f / (float)D));
}

// ---------------------------------------------------------------------------
// Kernel B: per batch-item (grid = 32, block = 512), fp32 throughout.
// PROVEN bit-exact (rel_err==0.0). DO NOT MODIFY ARITHMETIC.
// ---------------------------------------------------------------------------
__global__ void __launch_bounds__(512) mlp_sort_kernel(
    const float* __restrict__ W1, const float* __restrict__ b1,
    const float* __restrict__ W2, const float* __restrict__ b2) {
    const int b   = blockIdx.x;
    const int tid = threadIdx.x;

    __shared__ float ps[C];
    __shared__ float hs[H];
    __shared__ float ss[C];
    __shared__ int   si[C];

    ps[tid] = g_pooled[b * C + tid];
    __syncthreads();

    if (tid < H) {
        const float* __restrict__ w = W1 + tid * C;
        float acc = 0.f;
        for (int k = 0; k < C; k++) acc = fmaf(w[k], ps[k], acc);
        acc = __fadd_rn(acc, b1[tid]);
        hs[tid] = (acc >= 0.f) ? acc : __fmul_rn(0.01f, acc);
    }
    __syncthreads();

    {
        const float* __restrict__ w = W2 + tid * H;
        float acc = 0.f;
        for (int k = 0; k < H; k++) acc = fmaf(w[k], hs[k], acc);
        acc = __fadd_rn(acc, b2[tid]);
        float e = xla_cpu_expf(-acc);
        ss[tid] = __fdiv_rn(1.0f, __fadd_rn(1.0f, e));
        si[tid] = tid;
    }
    __syncthreads();

    // Bitonic sort, 512 elems, key = (score desc, idx asc).
    for (int k = 2; k <= C; k <<= 1) {
        for (int j = k >> 1; j > 0; j >>= 1) {
            const int i   = tid;
            const int ixj = i ^ j;
            if (ixj > i) {
                const float a_s = ss[i],  b_s = ss[ixj];
                const int   a_i = si[i],  b_i = si[ixj];
                const bool b_precedes_a = (b_s > a_s) || (b_s == a_s && b_i < a_i);
                const bool a_precedes_b = (a_s > b_s) || (a_s == b_s && a_i < b_i);
                const bool up = ((i & k) == 0);
                const bool do_swap = up ? b_precedes_a : a_precedes_b;
                if (do_swap) {
                    ss[i] = b_s; ss[ixj] = a_s;
                    si[i] = b_i; si[ixj] = a_i;
                }
            }
            __syncthreads();
        }
    }

    g_ord[b * C + tid] = si[tid];
}

// ---------------------------------------------------------------------------
// Kernel C: out[b,c,:] = x[b,c,:] + x[b, ord[b][c], :]
// b-major grid -> gathered read re-hits L2 (8 MiB/batch << 126 MB).
// All 8 loads issued before any arithmetic (8 outstanding LDG.128/thread);
// streaming stores (__stcs) keep out from evicting x slices in L2.
// ---------------------------------------------------------------------------
__global__ void __launch_bounds__(256) shuffle_add_kernel(
    const float* __restrict__ x, float* __restrict__ out) {
    const int row = blockIdx.x;          // b*512 + c
    const int b   = row >> 9;
    const int src = g_ord[row];

    const float4* __restrict__ xa =
        reinterpret_cast<const float4*>(x + (size_t)row * D);
    const float4* __restrict__ xb =
        reinterpret_cast<const float4*>(x + ((size_t)(b << 9) + src) * D);
    float4* __restrict__ o = reinterpret_cast<float4*>(out + (size_t)row * D);

    const int t = threadIdx.x;
    float4 a[4], g[4];
#pragma unroll
    for (int i = 0; i < 4; ++i) a[i] = xa[t + i * 256];
#pragma unroll
    for (int i = 0; i < 4; ++i) g[i] = xb[t + i * 256];
#pragma unroll
    for (int i = 0; i < 4; ++i) {
        float4 r;
        r.x = a[i].x + g[i].x;
        r.y = a[i].y + g[i].y;
        r.z = a[i].z + g[i].z;
        r.w = a[i].w + g[i].w;
        __stcs(&o[t + i * 256], r);
    }
}

// ---------------------------------------------------------------------------
extern "C" void kernel_launch(void* const* d_in, const int* in_sizes, int n_in,
                              void* d_out, int out_size) {
    const float* x  = (const float*)d_in[0];
    const float* W1 = (const float*)d_in[1];
    const float* b1 = (const float*)d_in[2];
    const float* W2 = (const float*)d_in[3];
    const float* b2 = (const float*)d_in[4];
    float* out = (float*)d_out;

    pool_kernel<<<NROWS / PR, PR>>>(x);
    mlp_sort_kernel<<<B, 512>>>(W1, b1, W2, b2);
    shuffle_add_kernel<<<NROWS, 256>>>(x, out);
}

// round 17
// speedup vs baseline: 1.3731x; 1.3482x over previous
#include <cuda_runtime.h>
#include <math.h>
#include <stdint.h>

// Problem shapes (fixed by the dataset)
#define B  32
#define C  512
#define D  4096
#define H  128        // hidden
#define NROWS (B * C) // 16384

// Pool kernel: warp-private cp.async pipelines (dynamic smem ring)
#define PR      128          // rows per block == threads per block (4 warps)
#define PCH     16           // columns per chunk
#define NCH     (D / PCH)    // 256 chunks
#define NSTAGE  8            // smem ring depth (power of 2)
#define LOOKAHEAD (NSTAGE - 1)       // 7 chunks in flight
#define SSTRIDE 20           // floats per row slot (16 + 4 pad; 80B, 16B-aligned)
#define STAGEF  (PR * SSTRIDE)       // floats per stage
#define RING_BYTES (NSTAGE * STAGEF * 4)   // 81920 B

// Scratch (no cudaMalloc allowed)
__device__ float g_pooled[B * C];
__device__ int   g_ord[B * C];

// ---------------------------------------------------------------------------
// Bit-faithful XLA-CPU vectorized expf. PROVEN: rel_err == 0.0. DO NOT MODIFY.
// ---------------------------------------------------------------------------
__device__ __forceinline__ float xla_cpu_expf(float x) {
    const float exp_hi = 88.3762626647950f;
    const float exp_lo = -88.3762626647949f;
    const float LOG2EF = 1.44269504088896341f;
    const float C1 = 0.693359375f;
    const float C2 = -2.12194440e-4f;
    const float p0 = 1.9875691500e-4f;
    const float p1 = 1.3981999507e-3f;
    const float p2 = 8.3334519073e-3f;
    const float p3 = 4.1665795894e-2f;
    const float p4 = 1.6666665459e-1f;
    const float p5 = 5.0000001201e-1f;

    x = fminf(fmaxf(x, exp_lo), exp_hi);

    float fx = __fadd_rn(__fmul_rn(x, LOG2EF), 0.5f);
    fx = floorf(fx);

    float tmp = __fmul_rn(fx, C1);
    float z   = __fmul_rn(fx, C2);
    x = __fsub_rn(x, tmp);
    x = __fsub_rn(x, z);
    z = __fmul_rn(x, x);

    float y = p0;
    y = __fadd_rn(__fmul_rn(y, x), p1);
    y = __fadd_rn(__fmul_rn(y, x), p2);
    y = __fadd_rn(__fmul_rn(y, x), p3);
    y = __fadd_rn(__fmul_rn(y, x), p4);
    y = __fadd_rn(__fmul_rn(y, x), p5);
    y = __fadd_rn(__fmul_rn(y, z), x);
    y = __fadd_rn(y, 1.0f);

    int n = (int)fx;
    y = __fmul_rn(y, __int_as_float((n + 127) << 23));
    return y;
}

// ---------------------------------------------------------------------------
// Kernel A: pooled[row] = (strict sequential fp32 sum over d) * (1/4096).
// IDENTICAL addition order to round 8 (bit-exact). Per-warp cp.async
// pipelines as in round 16, ring deepened to 8 stages (dynamic smem, 80 KB):
// 7 chunks in flight per warp (14 KB) vs 3 (6 KB) — in-flight bytes were the
// measured binder. Slot algebra: prologue commits chunks 0..6; each iter
// waits<=6 (chunk ch resident), refills chunk ch+7 into slot (ch+7)&7 =
// (ch-1)&7, whose reads finished before this iteration's __syncwarp.
// ---------------------------------------------------------------------------
__global__ void __launch_bounds__(PR) pool_kernel(const float* __restrict__ x) {
    extern __shared__ float ring[];   // [NSTAGE][PR * SSTRIDE]

    const int tid  = threadIdx.x;
    const int wid  = tid >> 5;
    const int lane = tid & 31;
    const int base = blockIdx.x * PR;
    const int wrow = wid << 5;
    const float4* __restrict__ x4 = reinterpret_cast<const float4*>(x);

#define ISSUE_STAGE(CH)                                                        \
    do {                                                                       \
        const int _s = (CH) & (NSTAGE - 1);                                    \
        _Pragma("unroll")                                                      \
        for (int _it = 0; _it < 4; ++_it) {                                    \
            const int _g  = lane + _it * 32;                                   \
            const int _r  = wrow + (_g >> 2);                                  \
            const int _c4 = _g & 3;                                            \
            const float4* _src = &x4[(size_t)(base + _r) * (D / 4)             \
                                     + (size_t)(CH) * (PCH / 4) + _c4];        \
            uint32_t _dst = (uint32_t)__cvta_generic_to_shared(                \
                &ring[_s * STAGEF + _r * SSTRIDE + _c4 * 4]);                  \
            asm volatile("cp.async.cg.shared.global [%0], [%1], 16;"           \
                         :: "r"(_dst), "l"(_src) : "memory");                  \
        }                                                                      \
        asm volatile("cp.async.commit_group;" ::: "memory");                   \
    } while (0)

#pragma unroll
    for (int p = 0; p < LOOKAHEAD; ++p) ISSUE_STAGE(p);

    float acc = 0.f;
    for (int ch = 0; ch < NCH; ++ch) {
        asm volatile("cp.async.wait_group %0;" :: "n"(LOOKAHEAD - 1) : "memory");
        __syncwarp();      // producers == this warp's lanes: visibility +
                           // fence prior iteration's reads before slot reuse.

        if (ch + LOOKAHEAD < NCH) {
            ISSUE_STAGE(ch + LOOKAHEAD);
        } else {
            asm volatile("cp.async.commit_group;" ::: "memory"); // empty group
        }

        // Strict sequential accumulation over this chunk's 16 columns.
        const int s = ch & (NSTAGE - 1);
        const float4* rowp =
            reinterpret_cast<const float4*>(&ring[s * STAGEF + tid * SSTRIDE]);
#pragma unroll
        for (int i4 = 0; i4 < PCH / 4; ++i4) {
            float4 v = rowp[i4];
            acc = __fadd_rn(acc, v.x);
            acc = __fadd_rn(acc, v.y);
            acc = __fadd_rn(acc, v.z);
            acc = __fadd_rn(acc, v.w);
        }
    }
#undef ISSUE_STAGE

    g_pooled[base + tid] = __fmul_rn(acc, (1.0f / (float)D));
}

// ---------------------------------------------------------------------------
// Kernel B: per batch-item (grid = 32, block = 512), fp32 throughout.
// ARITHMETIC IDENTICAL to the proven bit-exact version (sequential-k fmaf
// chains, bias-after, xla_cpu_expf logistic, bitonic sort). Only the W
// access path changed: W1/W2 k-tiles are staged through smem with coalesced
// float4 loads (the old direct loads had lane-stride = row-length -> 32 L1
// wavefronts per LDG, ~130K wavefronts total). Odd smem strides (65 / 17)
// make the dot-phase LDS conflict-free.
// ---------------------------------------------------------------------------
__global__ void __launch_bounds__(512) mlp_sort_kernel(
    const float* __restrict__ W1, const float* __restrict__ b1,
    const float* __restrict__ W2, const float* __restrict__ b2) {
    const int b   = blockIdx.x;
    const int tid = threadIdx.x;

    __shared__ float ps[C];
    __shared__ float hs[H];
    __shared__ float ss[C];
    __shared__ int   si[C];
    __shared__ float wt[8704];   // max(128*65, 512*17) floats = 34 KB

    ps[tid] = g_pooled[b * C + tid];
    __syncthreads();

    // ---- h = LeakyReLU(W1 @ pooled + b1), k-tiles of 64 ----
    const float4* __restrict__ W1_4 = reinterpret_cast<const float4*>(W1);
    float acc1 = 0.f;
#pragma unroll 1
    for (int kt = 0; kt < 8; ++kt) {
        // stage tile [j=0..127][kk=0..63] -> wt[j*65 + kk], coalesced f4 loads
#pragma unroll
        for (int it = 0; it < 4; ++it) {
            const int idx = tid + it * 512;      // 0..2047
            const int j   = idx >> 4;            // 0..127
            const int kk4 = idx & 15;            // 0..15
            float4 v = W1_4[j * (C / 4) + kt * 16 + kk4];
            float* dst = &wt[j * 65 + kk4 * 4];
            dst[0] = v.x; dst[1] = v.y; dst[2] = v.z; dst[3] = v.w;
        }
        __syncthreads();
        if (tid < H) {
            const float* wrow = &wt[tid * 65];
            const float* prow = &ps[kt * 64];
#pragma unroll
            for (int kk = 0; kk < 64; ++kk)
                acc1 = fmaf(wrow[kk], prow[kk], acc1);
        }
        __syncthreads();
    }
    if (tid < H) {
        float a = __fadd_rn(acc1, b1[tid]);
        hs[tid] = (a >= 0.f) ? a : __fmul_rn(0.01f, a);
    }
    __syncthreads();

    // ---- scores = logistic(W2 @ h + b2), k-tiles of 16 ----
    const float4* __restrict__ W2_4 = reinterpret_cast<const float4*>(W2);
    float acc2 = 0.f;
#pragma unroll 1
    for (int kt = 0; kt < 8; ++kt) {
        // stage tile [c=0..511][kk=0..15] -> wt[c*17 + kk]
#pragma unroll
        for (int it = 0; it < 4; ++it) {
            const int idx = tid + it * 512;      // 0..2047
            const int c   = idx >> 2;            // 0..511
            const int kk4 = idx & 3;             // 0..3
            float4 v = W2_4[c * (H / 4) + kt * 4 + kk4];
            float* dst = &wt[c * 17 + kk4 * 4];
            dst[0] = v.x; dst[1] = v.y; dst[2] = v.z; dst[3] = v.w;
        }
        __syncthreads();
        {
            const float* wrow = &wt[tid * 17];
            const float* hrow = &hs[kt * 16];
#pragma unroll
            for (int kk = 0; kk < 16; ++kk)
                acc2 = fmaf(wrow[kk], hrow[kk], acc2);
        }
        __syncthreads();
    }
    {
        float a = __fadd_rn(acc2, b2[tid]);
        float e = xla_cpu_expf(-a);
        ss[tid] = __fdiv_rn(1.0f, __fadd_rn(1.0f, e));
        si[tid] = tid;
    }
    __syncthreads();

    // Bitonic sort, 512 elems, key = (score desc, idx asc).
    for (int k = 2; k <= C; k <<= 1) {
        for (int j = k >> 1; j > 0; j >>= 1) {
            const int i   = tid;
            const int ixj = i ^ j;
            if (ixj > i) {
                const float a_s = ss[i],  b_s = ss[ixj];
                const int   a_i = si[i],  b_i = si[ixj];
                const bool b_precedes_a = (b_s > a_s) || (b_s == a_s && b_i < a_i);
                const bool a_precedes_b = (a_s > b_s) || (a_s == b_s && a_i < b_i);
                const bool up = ((i & k) == 0);
                const bool do_swap = up ? b_precedes_a : a_precedes_b;
                if (do_swap) {
                    ss[i] = b_s; ss[ixj] = a_s;
                    si[i] = b_i; si[ixj] = a_i;
                }
            }
            __syncthreads();
        }
    }

    g_ord[b * C + tid] = si[tid];
}

// ---------------------------------------------------------------------------
// Kernel C: out[b,c,:] = x[b,c,:] + x[b, ord[b][c], :]
// Unchanged from round 16 (b-major L2 reuse, batched loads, __stcs stores).
// ---------------------------------------------------------------------------
__global__ void __launch_bounds__(256) shuffle_add_kernel(
    const float* __restrict__ x, float* __restrict__ out) {
    const int row = blockIdx.x;          // b*512 + c
    const int b   = row >> 9;
    const int src = g_ord[row];

    const float4* __restrict__ xa =
        reinterpret_cast<const float4*>(x + (size_t)row * D);
    const float4* __restrict__ xb =
        reinterpret_cast<const float4*>(x + ((size_t)(b << 9) + src) * D);
    float4* __restrict__ o = reinterpret_cast<float4*>(out + (size_t)row * D);

    const int t = threadIdx.x;
    float4 a[4], g[4];
#pragma unroll
    for (int i = 0; i < 4; ++i) a[i] = xa[t + i * 256];
#pragma unroll
    for (int i = 0; i < 4; ++i) g[i] = xb[t + i * 256];
#pragma unroll
    for (int i = 0; i < 4; ++i) {
        float4 r;
        r.x = a[i].x + g[i].x;
        r.y = a[i].y + g[i].y;
        r.z = a[i].z + g[i].z;
        r.w = a[i].w + g[i].w;
        __stcs(&o[t + i * 256], r);
    }
}

// ---------------------------------------------------------------------------
extern "C" void kernel_launch(void* const* d_in, const int* in_sizes, int n_in,
                              void* d_out, int out_size) {
    const float* x  = (const float*)d_in[0];
    const float* W1 = (const float*)d_in[1];
    const float* b1 = (const float*)d_in[2];
    const float* W2 = (const float*)d_in[3];
    const float* b2 = (const float*)d_in[4];
    float* out = (float*)d_out;

    // Opt-in to >48KB dynamic smem for the pool ring (attribute set, not an
    // allocation; idempotent and capture-safe).
    cudaFuncSetAttribute(pool_kernel,
                         cudaFuncAttributeMaxDynamicSharedMemorySize,
                         RING_BYTES);

    pool_kernel<<<NROWS / PR, PR, RING_BYTES>>>(x);
    mlp_sort_kernel<<<B, 512>>>(W1, b1, W2, b2);
    shuffle_add_kernel<<<NROWS, 256>>>(x, out);
}